// round 4
// baseline (speedup 1.0000x reference)
#include <cuda_runtime.h>
#include <cstdint>

// Problem constants
#define BB 16
#define LL 2048
#define DD 64
#define DLAT 32
#define KK 16
#define DN 128

static const float SQC = 0.70710678118654752440f;

// ---------------- scratch (device globals, no allocation) ----------------
__device__ float g_z[BB * LL * DLAT];            // relu(seq@Wg)      4 MB
__device__ float g_v[BB * KK * LL];              // v[b][kk][l]       2 MB
__device__ float g_det[BB * KK * 1920];          // details, packed
__device__ float g_app[BB * KK * 1920];          // approxs, packed
__device__ float g_curA[(size_t)BB * DLAT * KK * LL];   // 64 MB ping
__device__ float g_curB[(size_t)BB * DLAT * KK * LL];   // 64 MB pong

// ---------------- K1: z = relu(seq @ Wg) ----------------
__global__ void k_z(const float* __restrict__ seq, const float* __restrict__ Wg) {
    __shared__ float sWg[DD * DLAT];   // 8 KB
    __shared__ float srow[8 * DD];     // 2 KB
    int tid = threadIdx.x;
    for (int i = tid; i < DD * DLAT; i += 256) sWg[i] = Wg[i];
    int row0 = blockIdx.x * 8;
    for (int i = tid; i < 8 * DD; i += 256) srow[i] = seq[(size_t)row0 * DD + i];
    __syncthreads();
    int r = tid >> 5;
    int j = tid & 31;
    float acc = 0.f;
#pragma unroll
    for (int Dd = 0; Dd < DD; ++Dd) acc += srow[r * DD + Dd] * sWg[Dd * DLAT + j];
    g_z[(size_t)(row0 + r) * DLAT + j] = fmaxf(acc, 0.f);
}

// ---------------- K2: v[b,kk,l] = sum_D relu(z . Wh[:,D*16+kk]) * der[b,l,D] ----------------
// block: 128 threads = (kkgrp 0..3) x (lt 0..31); one b, 32 l positions.
__global__ void k_v(const float* __restrict__ coeffs, const float* __restrict__ tme,
                    const float* __restrict__ ts, const float* __restrict__ Wh, int Lts) {
    __shared__ __align__(16) float sWh[32 * 256];  // 32 KB (D-chunk of 16 -> 256 cols)
    __shared__ float sder[32 * 65];                // padded stride, ~8.3 KB
    __shared__ int   si[32];
    __shared__ float sinv[32];

    int tid = threadIdx.x;
    int b   = blockIdx.x >> 6;
    int l0  = (blockIdx.x & 63) << 5;

    if (tid < 32) {
        float t = tme[l0 + tid];
        int lo = 0, hi = Lts;
        while (lo < hi) { int mid = (lo + hi) >> 1; if (ts[mid] <= t) lo = mid + 1; else hi = mid; }
        int i = lo - 1;
        if (i < 0) i = 0;
        if (i > Lts - 2) i = Lts - 2;
        si[tid]   = i;
        sinv[tid] = 1.f / (ts[i + 1] - ts[i]);
    }
    __syncthreads();
    for (int e = tid; e < 2048; e += 128) {
        int lt = e >> 6, Dg = e & 63;
        int i  = si[lt];
        float a = coeffs[((size_t)b * LL + i + 1) * DD + Dg];
        float c = coeffs[((size_t)b * LL + i) * DD + Dg];
        sder[lt * 65 + Dg] = (a - c) * sinv[lt];
    }

    int kk0 = (tid & 3) * 4;
    int lt  = tid >> 2;

    float zr[32];
    {
        const float4* zp = (const float4*)(g_z + ((size_t)b * LL + l0 + lt) * DLAT);
#pragma unroll
        for (int q = 0; q < 8; ++q) {
            float4 z4 = zp[q];
            zr[q * 4 + 0] = z4.x; zr[q * 4 + 1] = z4.y;
            zr[q * 4 + 2] = z4.z; zr[q * 4 + 3] = z4.w;
        }
    }

    float acc0 = 0.f, acc1 = 0.f, acc2 = 0.f, acc3 = 0.f;
#pragma unroll 1
    for (int ch = 0; ch < 4; ++ch) {
        __syncthreads();
        const float4* src4 = (const float4*)Wh + ch * 64;
        for (int e = tid; e < 2048; e += 128) {
            int ddr = e >> 6, c4 = e & 63;
            ((float4*)sWh)[ddr * 64 + c4] = src4[(size_t)ddr * 256 + c4];
        }
        __syncthreads();
#pragma unroll 2
        for (int Dl = 0; Dl < 16; ++Dl) {
            float h0 = 0.f, h1 = 0.f, h2 = 0.f, h3 = 0.f;
            const float* wbase = sWh + Dl * 16 + kk0;
#pragma unroll
            for (int ddq = 0; ddq < 32; ++ddq) {
                float4 w = *(const float4*)(wbase + ddq * 256);
                h0 += zr[ddq] * w.x; h1 += zr[ddq] * w.y;
                h2 += zr[ddq] * w.z; h3 += zr[ddq] * w.w;
            }
            float dv = sder[lt * 65 + ch * 16 + Dl];
            acc0 += fmaxf(h0, 0.f) * dv;
            acc1 += fmaxf(h1, 0.f) * dv;
            acc2 += fmaxf(h2, 0.f) * dv;
            acc3 += fmaxf(h3, 0.f) * dv;
        }
    }
    size_t vb = (size_t)b * KK;
    g_v[(vb + kk0 + 0) * LL + l0 + lt] = acc0;
    g_v[(vb + kk0 + 1) * LL + l0 + lt] = acc1;
    g_v[(vb + kk0 + 2) * LL + l0 + lt] = acc2;
    g_v[(vb + kk0 + 3) * LL + l0 + lt] = acc3;
}

// ---------------- K3: 4-level Haar decomposition of v ----------------
__global__ void k_haar() {
    __shared__ float s0[2048];
    __shared__ float s1[1024];
    int bk  = blockIdx.x;       // b*16+kk
    int tid = threadIdx.x;
    const float* row = g_v + (size_t)bk * LL;
    for (int i = tid; i < 2048; i += 128) s0[i] = row[i];
    __syncthreads();
    int n = 2048, off = 0;
    float* src = s0;
    float* dst = s1;
    for (int lev = 0; lev < 4; ++lev) {
        int half = n >> 1;
        for (int t = tid; t < half; t += 128) {
            float a = src[2 * t], bv = src[2 * t + 1];
            float cA = (a + bv) * 0.70710678118654752440f;
            float cD = (a - bv) * 0.70710678118654752440f;
            dst[t] = cA;
            g_det[(size_t)bk * 1920 + off + t] = cD;
            g_app[(size_t)bk * 1920 + off + t] = cA;
        }
        __syncthreads();
        off += half; n = half;
        float* tmp = src; src = dst; dst = tmp;
    }
}

// ---------------- K4: dense chain (3 rounds) ----------------
// round 0: app(level3) -> curA ; round 1: curA -> curB ; round 2: curB -> curA
__global__ void k_dense(const float* __restrict__ W, int round) {
    __shared__ __align__(16) float sx[DN * 16];  // [q][b], 8 KB
    int tid = threadIdx.x;                       // 128 threads
    int dd  = blockIdx.x >> 4;
    int kk  = blockIdx.x & 15;
    const float* prev = (round == 1) ? g_curA : g_curB;
    float* outp       = (round == 1) ? g_curB : g_curA;

    for (int e = tid; e < 2048; e += 128) {
        int b = e >> 7, q = e & 127;
        float v;
        if (round == 0) v = g_app[(size_t)(b * 16 + kk) * 1920 + 1792 + q];
        else            v = prev[((size_t)(b * 32 + dd) * 16 + kk) * DN + q];
        sx[q * 16 + b] = v;
    }
    __syncthreads();

    int t = tid;
    float acc[16];
#pragma unroll
    for (int i = 0; i < 16; ++i) acc[i] = 0.f;
    const float4* w4 = (const float4*)(W + ((size_t)(dd * 16 + kk) * DN + t) * DN);
#pragma unroll 4
    for (int q4 = 0; q4 < 32; ++q4) {
        float4 wq = w4[q4];
#pragma unroll
        for (int s = 0; s < 4; ++s) {
            float wv = (s == 0) ? wq.x : (s == 1) ? wq.y : (s == 2) ? wq.z : wq.w;
            const float4* xv = (const float4*)&sx[(q4 * 4 + s) * 16];
#pragma unroll
            for (int b4 = 0; b4 < 4; ++b4) {
                float4 x = xv[b4];
                acc[b4 * 4 + 0] += wv * x.x;
                acc[b4 * 4 + 1] += wv * x.y;
                acc[b4 * 4 + 2] += wv * x.z;
                acc[b4 * 4 + 3] += wv * x.w;
            }
        }
    }
#pragma unroll
    for (int b = 0; b < 16; ++b)
        outp[((size_t)(b * 32 + dd) * 16 + kk) * DN + t] = acc[b];
}

// ---------------- K5: fused LC level (init + 3 conv rounds + add-cur + haar_rec) ----------------
// grid: B * 32 * (16/G); 256 threads.  Entirely in SMEM per (b,dd,kk-group).
__global__ void k_lc(const float* __restrict__ lc_w, const float* __restrict__ lc_b,
                     int lev, int Ll, int G, int off) {
    __shared__ float xbuf[2][2112];   // padded rows: G*2*(Ll+4) <= 2112
    __shared__ float sw[3][1280];     // 3 rounds x G*160 weights
    __shared__ float sb[3][128];      // 3 rounds x G*16 biases
    int tid = threadIdx.x;
    int kPerG = 16 / G;
    int perB  = 32 * kPerG;
    int b   = blockIdx.x / perB;
    int rem = blockIdx.x - b * perB;
    int dd  = rem / kPerG;
    int kg0 = (rem - dd * kPerG) * G;

    const float* prevC = (lev & 1) ? g_curA : g_curB;
    float*       nextC = (lev & 1) ? g_curB : g_curA;

    int wtot = 3 * G * 160;
    for (int e = tid; e < wtot; e += 256) {
        int j  = e / (G * 160);
        int r  = e - j * (G * 160);
        int kg = r / 160;
        int w  = r - kg * 160;
        sw[j][kg * 160 + w] =
            lc_w[((size_t)((lev * 3 + j) * 32 + dd) * 16 + (kg0 + kg)) * 160 + w];
    }
    int btot = 3 * G * 16;
    for (int e = tid; e < btot; e += 256) {
        int j  = e / (G * 16);
        int r  = e - j * (G * 16);
        int kg = r / 16;
        int w  = r - kg * 16;
        sb[j][kg * 16 + w] =
            lc_b[((size_t)((lev * 3 + j) * 32 + dd) * 16 + (kg0 + kg)) * 16 + w];
    }
    for (int e = tid; e < 2 * 2112; e += 256) ((float*)xbuf)[e] = 0.f;
    __syncthreads();

    int stride = Ll + 4;
    // init: row = kg*2 + i ; i=0 -> details, i=1 -> approxs
    for (int e = tid; e < G * 2 * Ll; e += 256) {
        int row = e / Ll;
        int t   = e - row * Ll;
        int kg  = row >> 1;
        int i   = row & 1;
        int kk  = kg0 + kg;
        const float* srcg = (i == 0) ? g_det : g_app;
        xbuf[0][row * stride + 2 + t] = srcg[(size_t)(b * 16 + kk) * 1920 + off + t];
    }
    __syncthreads();

    int R      = Ll >> 3;
    int combos = G * 16;          // G * 2(out) * 8(seg)
    int tpc    = 256 / combos;    // threads per combo, tpc*8 == R
    int sub    = tid % tpc;
    int combo  = tid / tpc;
    int kg  = combo >> 4;
    int o   = (combo >> 3) & 1;
    int seg = combo & 7;
    int t0  = seg * R + sub * 8;

    int src = 0;
    for (int j = 0; j < 3; ++j) {
        float wr[10];
#pragma unroll
        for (int i2 = 0; i2 < 2; ++i2)
#pragma unroll
            for (int f = 0; f < 5; ++f)
                wr[i2 * 5 + f] = sw[j][kg * 160 + o * 80 + i2 * 40 + seg * 5 + f];
        float bias = sb[j][kg * 16 + o * 8 + seg];

        const float* x0 = &xbuf[src][(kg * 2 + 0) * stride + t0];
        const float* x1 = &xbuf[src][(kg * 2 + 1) * stride + t0];
        float* dst = &xbuf[src ^ 1][(kg * 2 + o) * stride + 2 + t0];

        float a0 = x0[0], a1 = x0[1], a2 = x0[2], a3 = x0[3];
        float c0 = x1[0], c1 = x1[1], c2 = x1[2], c3 = x1[3];
#pragma unroll
        for (int t = 0; t < 8; ++t) {
            float a4 = x0[t + 4];
            float c4 = x1[t + 4];
            float acc = bias;
            acc += wr[0] * a0 + wr[1] * a1 + wr[2] * a2 + wr[3] * a3 + wr[4] * a4;
            acc += wr[5] * c0 + wr[6] * c1 + wr[7] * c2 + wr[8] * c3 + wr[9] * c4;
            dst[t] = fmaxf(acc, 0.f);
            a0 = a1; a1 = a2; a2 = a3; a3 = a4;
            c0 = c1; c1 = c2; c2 = c3; c3 = c4;
        }
        __syncthreads();
        src ^= 1;
    }

    // X1 = chan1 + cur_prev ; X0 = chan0 ; haar_rec -> next cur (len 2*Ll)
    for (int e = tid; e < G * Ll; e += 256) {
        int kg2 = e / Ll;
        int t   = e - kg2 * Ll;
        int kk  = kg0 + kg2;
        float X0 = xbuf[src][(kg2 * 2 + 0) * stride + 2 + t];
        float X1 = xbuf[src][(kg2 * 2 + 1) * stride + 2 + t] +
                   prevC[((size_t)(b * 32 + dd) * 16 + kk) * Ll + t];
        float ev = (X1 + X0) * 0.70710678118654752440f;
        float od = (X1 - X0) * 0.70710678118654752440f;
        float2 st2 = make_float2(ev, od);
        *(float2*)&nextC[((size_t)(b * 32 + dd) * 16 + kk) * (2 * Ll) + 2 * t] = st2;
    }
}

// ---------------- K6: out = sum_k cur; U = out^T @ Wrev ----------------
__global__ void k_final(const float* __restrict__ Wrev, float* __restrict__ out) {
    __shared__ float sW[DLAT * DD];  // 8 KB
    __shared__ float ss[DLAT * 32];  // 4 KB
    int tid = threadIdx.x;
    int b   = blockIdx.x >> 6;
    int t0  = (blockIdx.x & 63) << 5;
    for (int e = tid; e < DLAT * DD; e += 256) sW[e] = Wrev[e];
    for (int e = tid; e < 1024; e += 256) {
        int dd = e >> 5, tt = e & 31;
        float s = 0.f;
        size_t base = ((size_t)(b * 32 + dd) * 16) * LL + t0 + tt;
#pragma unroll
        for (int kk = 0; kk < 16; ++kk) s += g_curA[base + (size_t)kk * LL];
        ss[dd * 32 + tt] = s;
    }
    __syncthreads();
    for (int e = tid; e < 2048; e += 256) {
        int tt = e >> 6, Dj = e & 63;
        float acc = 0.f;
#pragma unroll
        for (int dd = 0; dd < DLAT; ++dd) acc += ss[dd * 32 + tt] * sW[dd * DD + Dj];
        out[((size_t)b * LL + t0 + tt) * DD + Dj] = acc;
    }
}

// ---------------- launch ----------------
extern "C" void kernel_launch(void* const* d_in, const int* in_sizes, int n_in,
                              void* d_out, int out_size) {
    const float* seq    = (const float*)d_in[0];
    const float* coeffs = (const float*)d_in[1];
    const float* tme    = (const float*)d_in[2];
    const float* ts     = (const float*)d_in[3];
    const float* Wg     = (const float*)d_in[4];
    const float* Wh     = (const float*)d_in[5];
    const float* denseW = (const float*)d_in[6];
    const float* lcw    = (const float*)d_in[7];
    const float* lcb    = (const float*)d_in[8];
    const float* Wrev   = (const float*)d_in[9];
    float* out = (float*)d_out;
    int Lts = in_sizes[3];

    k_z<<<(BB * LL) / 8, 256>>>(seq, Wg);
    k_v<<<BB * (LL / 32), 128>>>(coeffs, tme, ts, Wh, Lts);
    k_haar<<<BB * KK, 128>>>();
    for (int r = 0; r < 3; ++r)
        k_dense<<<DLAT * KK, 128>>>(denseW + (size_t)r * DLAT * KK * DN * DN, r);

    const int Lls[4]  = {1024, 512, 256, 128};
    const int Gs[4]   = {1, 2, 4, 8};
    const int offs[4] = {0, 1024, 1536, 1792};
    for (int lev = 3; lev >= 0; --lev) {
        int G = Gs[lev];
        int blocks = BB * 32 * (16 / G);
        k_lc<<<blocks, 256>>>(lcw, lcb, lev, Lls[lev], G, offs[lev]);
    }
    k_final<<<BB * (LL / 32), 256>>>(Wrev, out);
}